// round 4
// baseline (speedup 1.0000x reference)
#include <cuda_runtime.h>

#define Ln 16384
#define BATCH 64
#define NT 1024
#define CHUNK 16
#define NIMF 6
#define MAXIT 12
#define TOLF 0.05
#define NEG_INF (-3.402823466e38f)
#define POS_INF (3.402823466e38f)
#define IDX(i) ((i)+((i)>>4))
#define PADL (Ln+(Ln>>4))

__device__ unsigned g_count;
__device__ float g_part[2][4][BATCH];
__device__ float g_res[BATCH*Ln];

__global__ void emd_init() { g_count = 0u; }

// block-wide exclusive scan over per-thread floats; ismax=1 -> max (ident -inf), else min (ident +inf)
__device__ __forceinline__ float bscan_ex(float v, int ismax, float* s_w) {
  const float ident = ismax ? NEG_INF : POS_INF;
  int lane = threadIdx.x & 31, wid = threadIdx.x >> 5;
  __syncthreads();
  float incl = v;
#pragma unroll
  for (int o = 1; o < 32; o <<= 1) {
    float u = __shfl_up_sync(0xffffffffu, incl, o);
    if (lane >= o) incl = ismax ? fmaxf(incl, u) : fminf(incl, u);
  }
  if (lane == 31) s_w[wid] = incl;
  __syncthreads();
  if (wid == 0) {
    float wi = s_w[lane];
#pragma unroll
    for (int o = 1; o < 32; o <<= 1) {
      float u = __shfl_up_sync(0xffffffffu, wi, o);
      if (lane >= o) wi = ismax ? fmaxf(wi, u) : fminf(wi, u);
    }
    float we = __shfl_up_sync(0xffffffffu, wi, 1);
    if (lane == 0) we = ident;
    s_w[lane] = we;
  }
  __syncthreads();
  float e = __shfl_up_sync(0xffffffffu, incl, 1);
  if (lane == 0) e = ident;
  float wp = s_w[wid];
  return ismax ? fmaxf(wp, e) : fminf(wp, e);
}

// exclusive suffix-min over per-thread floats (min of values of threads > t)
__device__ __forceinline__ float brev_ex_min(float v, float* s_x, float* s_w) {
  int t = threadIdx.x;
  __syncthreads();
  s_x[t] = v;
  __syncthreads();
  float rv = s_x[NT - 1 - t];
  float re = bscan_ex(rv, 0, s_w);   // internal syncs protect s_x reuse
  s_x[NT - 1 - t] = re;
  __syncthreads();
  return s_x[t];
}

__device__ __forceinline__ float bsum(float v, float* s_w) {
  int lane = threadIdx.x & 31, wid = threadIdx.x >> 5;
  __syncthreads();
#pragma unroll
  for (int o = 16; o > 0; o >>= 1) v += __shfl_down_sync(0xffffffffu, v, o);
  if (lane == 0) s_w[wid] = v;
  __syncthreads();
  if (wid == 0) {
    float x = s_w[lane];
#pragma unroll
    for (int o = 16; o > 0; o >>= 1) x += __shfl_down_sync(0xffffffffu, x, o);
    if (lane == 0) s_w[0] = x;
  }
  __syncthreads();
  return s_w[0];
}

__device__ __forceinline__ void gbar(unsigned target) {
  __syncthreads();
  if (threadIdx.x == 0) {
    __threadfence();
    atomicAdd(&g_count, 1u);
    while (*((volatile unsigned*)&g_count) < target) __nanosleep(64);
    __threadfence();
  }
  __syncthreads();
}

// np.interp through masked peaks: l = inclusive prev-peak (-1 none), r = inclusive next-peak (Ln none)
__device__ __forceinline__ float ienv(const float* sh, float lf, float rf, int i) {
  int l = (int)lf, r = (int)rf;
  if (r >= Ln) return sh[IDX(l < 0 ? 0 : l)];
  if (l < 0) return sh[IDX(r)];
  float vl = sh[IDX(l)], vr = sh[IDX(r)];
  int den = r - l;
  if (den <= 0) return vl;
  return vl + ((float)(i - l) / (float)den) * (vr - vl);
}

__global__ void __launch_bounds__(NT, 1)
emd_main(const float* __restrict__ x, float* __restrict__ out) {
  extern __shared__ float dsm[];
  float* shH = dsm;
  float* shE = shH + PADL;
  int* shT = (int*)(shE + PADL);
  __shared__ float s_w[32];
  __shared__ float s_x[NT];
  __shared__ float s_sc[2];

  const int t = threadIdx.x, row = blockIdx.x;
  const int rb = row * Ln, base = t * CHUNK;
  unsigned nbar = 0;
  int slot = 0;

  for (int i = t; i < Ln; i += NT) g_res[rb + i] = x[rb + i];

  bool done = false;
  for (int k = 0; k < NIMF; k++) {
    float* outk = out + (size_t)k * BATCH * Ln + rb;
    if (done) {
      for (int i = t; i < Ln; i += NT) outk[i] = 0.f;
      continue;
    }
    for (int i = t; i < Ln; i += NT) shH[IDX(i)] = g_res[rb + i];
    __syncthreads();

    // -------- sifting --------
    for (int it = 0; it < MAXIT; it++) {
      // pass 1: masks, per-thread last/first peak idx, counts, sum(h^2)
      float a = (base > 0) ? shH[IDX(base - 1)] : 0.f;
      float b = shH[IDX(base)];
      float lu = -1.f, ll = -1.f, fu = (float)Ln, fl = (float)Ln;
      float cu = 0.f, cl = 0.f, h2 = 0.f;
#pragma unroll
      for (int j = 0; j < CHUNK; j++) {
        int i = base + j;
        float c = (i + 1 < Ln) ? shH[IDX(i + 1)] : 0.f;
        bool valid = (i > 0) && (i < Ln - 1);
        if (valid && b > a && b > c) { lu = (float)i; cu += 1.f; if (fu == (float)Ln) fu = (float)i; }
        if (valid && b < a && b < c) { ll = (float)i; cl += 1.f; if (fl == (float)Ln) fl = (float)i; }
        h2 += b * b;
        a = b; b = c;
      }
      float preU = fmaxf(bscan_ex(lu, 1, s_w), -1.f);
      float preL = fmaxf(bscan_ex(ll, 1, s_w), -1.f);
      float sufU = fminf(brev_ex_min(fu, s_x, s_w), (float)Ln);
      float sufL = fminf(brev_ex_min(fl, s_x, s_w), (float)Ln);
      float cuT = bsum(cu, s_w);
      float clT = bsum(cl, s_w);

      float m2 = 0.f;
      if (cuT >= 2.f && clT >= 2.f) {
        // pass 2 fwd: store inclusive last-peak idx (both envs packed)
        float a2 = (base > 0) ? shH[IDX(base - 1)] : 0.f, b2 = shH[IDX(base)];
        float lu2 = preU, ll2 = preL;
#pragma unroll
        for (int j = 0; j < CHUNK; j++) {
          int i = base + j;
          float c2 = (i + 1 < Ln) ? shH[IDX(i + 1)] : 0.f;
          bool valid = (i > 0) && (i < Ln - 1);
          if (valid && b2 > a2 && b2 > c2) lu2 = (float)i;
          if (valid && b2 < a2 && b2 < c2) ll2 = (float)i;
          shT[IDX(i)] = ((int)lu2 + 1) | (((int)ll2 + 1) << 16);
          a2 = b2; b2 = c2;
        }
        // pass 3 bwd: inclusive next-peak, fused mean
        int i0 = base + CHUNK - 1;
        float b3 = shH[IDX(i0)];
        float c3 = (i0 + 1 < Ln) ? shH[IDX(i0 + 1)] : 0.f;
        float ru = sufU, rl = sufL;
#pragma unroll
        for (int j = CHUNK - 1; j >= 0; j--) {
          int i = base + j;
          float a3 = (i > 0) ? shH[IDX(i - 1)] : 0.f;
          bool valid = (i > 0) && (i < Ln - 1);
          if (valid && b3 > a3 && b3 > c3) ru = (float)i;
          if (valid && b3 < a3 && b3 < c3) rl = (float)i;
          unsigned pk = (unsigned)shT[IDX(i)];
          float lux = (float)((int)(pk & 0xffffu) - 1);
          float llx = (float)((int)(pk >> 16) - 1);
          float m = 0.5f * (ienv(shH, lux, ru, i) + ienv(shH, llx, rl, i));
          shE[IDX(i)] = m;
          m2 += m * m;
          c3 = b3; b3 = a3;
        }
      } else {
        // rare path: per-envelope, with cummax/cummin fallback (<2 peaks)
        if (cuT >= 2.f) {
          float a2 = (base > 0) ? shH[IDX(base - 1)] : 0.f, b2 = shH[IDX(base)];
          float lu2 = preU;
#pragma unroll
          for (int j = 0; j < CHUNK; j++) {
            int i = base + j;
            float c2 = (i + 1 < Ln) ? shH[IDX(i + 1)] : 0.f;
            if (i > 0 && i < Ln - 1 && b2 > a2 && b2 > c2) lu2 = (float)i;
            shT[IDX(i)] = (int)lu2;
            a2 = b2; b2 = c2;
          }
          int i0 = base + CHUNK - 1;
          float b3 = shH[IDX(i0)], c3 = (i0 + 1 < Ln) ? shH[IDX(i0 + 1)] : 0.f, ru = sufU;
#pragma unroll
          for (int j = CHUNK - 1; j >= 0; j--) {
            int i = base + j;
            float a3 = (i > 0) ? shH[IDX(i - 1)] : 0.f;
            if (i > 0 && i < Ln - 1 && b3 > a3 && b3 > c3) ru = (float)i;
            shE[IDX(i)] = ienv(shH, (float)shT[IDX(i)], ru, i);
            c3 = b3; b3 = a3;
          }
        } else {
          float mx = NEG_INF;
#pragma unroll
          for (int j = 0; j < CHUNK; j++) mx = fmaxf(mx, shH[IDX(base + j)]);
          float run = bscan_ex(mx, 1, s_w);
#pragma unroll
          for (int j = 0; j < CHUNK; j++) { run = fmaxf(run, shH[IDX(base + j)]); shE[IDX(base + j)] = run; }
        }
        if (clT >= 2.f) {
          float a2 = (base > 0) ? shH[IDX(base - 1)] : 0.f, b2 = shH[IDX(base)];
          float ll2 = preL;
#pragma unroll
          for (int j = 0; j < CHUNK; j++) {
            int i = base + j;
            float c2 = (i + 1 < Ln) ? shH[IDX(i + 1)] : 0.f;
            if (i > 0 && i < Ln - 1 && b2 < a2 && b2 < c2) ll2 = (float)i;
            shT[IDX(i)] = (int)ll2;
            a2 = b2; b2 = c2;
          }
          int i0 = base + CHUNK - 1;
          float b3 = shH[IDX(i0)], c3 = (i0 + 1 < Ln) ? shH[IDX(i0 + 1)] : 0.f, rl = sufL;
#pragma unroll
          for (int j = CHUNK - 1; j >= 0; j--) {
            int i = base + j;
            float a3 = (i > 0) ? shH[IDX(i - 1)] : 0.f;
            if (i > 0 && i < Ln - 1 && b3 < a3 && b3 < c3) rl = (float)i;
            float m = 0.5f * (shE[IDX(i)] + ienv(shH, (float)shT[IDX(i)], rl, i));
            shE[IDX(i)] = m;
            m2 += m * m;
            c3 = b3; b3 = a3;
          }
        } else {
          float mn = POS_INF;
#pragma unroll
          for (int j = 0; j < CHUNK; j++) mn = fminf(mn, shH[IDX(base + j)]);
          float run = bscan_ex(mn, 0, s_w);
#pragma unroll
          for (int j = 0; j < CHUNK; j++) {
            run = fminf(run, shH[IDX(base + j)]);
            float m = 0.5f * (shE[IDX(base + j)] + run);
            shE[IDX(base + j)] = m;
            m2 += m * m;
          }
        }
      }

      // global sd = sum(mean^2)/(sum(h^2)+eps) over whole batch
      float m2T = bsum(m2, s_w);
      float h2T = bsum(h2, s_w);
      if (t == 0) { __stcg(&g_part[slot][0][row], m2T); __stcg(&g_part[slot][1][row], h2T); }
      nbar++;
      gbar(nbar * (unsigned)BATCH);
      if (t == 0) {
        double A = 0.0, B = 0.0;
        for (int r = 0; r < BATCH; r++) {
          A += (double)__ldcg(&g_part[slot][0][r]);
          B += (double)__ldcg(&g_part[slot][1][r]);
        }
        s_sc[0] = (A / (B + 1e-8) < TOLF) ? 1.f : 0.f;
      }
      __syncthreads();
      slot ^= 1;
      if (s_sc[0] != 0.f) break;   // identical across all blocks (same global data, same order)
#pragma unroll
      for (int j = 0; j < CHUNK; j++) shH[IDX(base + j)] -= shE[IDX(base + j)];
      __syncthreads();
    }

    // emit imf = h, res -= h; stage new res in shE for diff pass
    for (int i = t; i < Ln; i += NT) {
      float h = shH[IDX(i)];
      float r = g_res[rb + i] - h;
      outk[i] = h;
      g_res[rb + i] = r;
      shE[IDX(i)] = r;
    }
    __syncthreads();

    // flatness: var(diff(res), ddof=1) < TOL * var(res, ddof=1), global over batch
    float s1 = 0.f, s2 = 0.f, d1 = 0.f, d2 = 0.f;
#pragma unroll
    for (int j = 0; j < CHUNK; j++) {
      int i = base + j;
      float v = shE[IDX(i)];
      s1 += v; s2 += v * v;
      if (i < Ln - 1) { float d = shE[IDX(i + 1)] - v; d1 += d; d2 += d * d; }
    }
    s1 = bsum(s1, s_w); s2 = bsum(s2, s_w);
    d1 = bsum(d1, s_w); d2 = bsum(d2, s_w);
    if (t == 0) {
      __stcg(&g_part[slot][0][row], s1); __stcg(&g_part[slot][1][row], s2);
      __stcg(&g_part[slot][2][row], d1); __stcg(&g_part[slot][3][row], d2);
    }
    nbar++;
    gbar(nbar * (unsigned)BATCH);
    if (t == 0) {
      double S1 = 0, S2 = 0, D1 = 0, D2 = 0;
      for (int r = 0; r < BATCH; r++) {
        S1 += (double)__ldcg(&g_part[slot][0][r]); S2 += (double)__ldcg(&g_part[slot][1][r]);
        D1 += (double)__ldcg(&g_part[slot][2][r]); D2 += (double)__ldcg(&g_part[slot][3][r]);
      }
      double N = (double)BATCH * Ln, Nd = (double)BATCH * (Ln - 1);
      double vr = (S2 - S1 * S1 / N) / (N - 1.0);
      double vd = (D2 - D1 * D1 / Nd) / (Nd - 1.0);
      s_sc[0] = (vd < TOLF * vr) ? 1.f : 0.f;
    }
    __syncthreads();
    slot ^= 1;
    if (s_sc[0] != 0.f) done = true;
  }

  // residual plane
  for (int i = t; i < Ln; i += NT) out[(size_t)NIMF * BATCH * Ln + rb + i] = g_res[rb + i];
}

extern "C" void kernel_launch(void* const* d_in, const int* in_sizes, int n_in,
                              void* d_out, int out_size) {
  const float* x = (const float*)d_in[0];
  float* out = (float*)d_out;
  (void)in_sizes; (void)n_in; (void)out_size;
  cudaFuncSetAttribute(emd_main, cudaFuncAttributeMaxDynamicSharedMemorySize, PADL * 3 * 4);
  emd_init<<<1, 1>>>();
  emd_main<<<BATCH, NT, PADL * 3 * 4>>>(x, out);
}

// round 6
// speedup vs baseline: 1.5741x; 1.5741x over previous
#include <cuda_runtime.h>

#define Ln 16384
#define BATCH 64
#define NT 1024
#define CHUNK 16
#define NIMF 6
#define MAXIT 12
#define TOLF 0.05
#define NEG_INF (-3.402823466e38f)
#define POS_INF (3.402823466e38f)
#define IDX(i) ((i)+((i)>>4))
#define PADL (Ln+(Ln>>4))

__device__ unsigned g_ep[BATCH];
__device__ float g_part[2][4][BATCH];
__device__ float g_res[BATCH*Ln];

__global__ void emd_init() { if (threadIdx.x < BATCH) g_ep[threadIdx.x] = 0u; }

// ---------- block primitives ----------

// generic single-value exclusive prefix scan (for rare fallback paths)
__device__ __forceinline__ float bscan_ex(float v, int ismax, float* s_w) {
  const float ident = ismax ? NEG_INF : POS_INF;
  int lane = threadIdx.x & 31, wid = threadIdx.x >> 5;
  __syncthreads();
  float incl = v;
#pragma unroll
  for (int o = 1; o < 32; o <<= 1) {
    float u = __shfl_up_sync(0xffffffffu, incl, o);
    if (lane >= o) incl = ismax ? fmaxf(incl, u) : fminf(incl, u);
  }
  if (lane == 31) s_w[wid] = incl;
  __syncthreads();
  if (wid == 0) {
    float wi = s_w[lane];
#pragma unroll
    for (int o = 1; o < 32; o <<= 1) {
      float u = __shfl_up_sync(0xffffffffu, wi, o);
      if (lane >= o) wi = ismax ? fmaxf(wi, u) : fminf(wi, u);
    }
    float we = __shfl_up_sync(0xffffffffu, wi, 1);
    if (lane == 0) we = ident;
    s_w[lane] = we;
  }
  __syncthreads();
  float e = __shfl_up_sync(0xffffffffu, incl, 1);
  if (lane == 0) e = ident;
  float wp = s_w[wid];
  return ismax ? fmaxf(wp, e) : fminf(wp, e);
}

// fused dual exclusive prefix MAX scan; also returns inclusive totals
__device__ __forceinline__ void bscan2_ex_max(float v1, float v2, float* s_w,
                                              float& e1, float& e2,
                                              float& tot1, float& tot2) {
  int lane = threadIdx.x & 31, wid = threadIdx.x >> 5;
  __syncthreads();
  float i1 = v1, i2 = v2;
#pragma unroll
  for (int o = 1; o < 32; o <<= 1) {
    float u1 = __shfl_up_sync(0xffffffffu, i1, o);
    float u2 = __shfl_up_sync(0xffffffffu, i2, o);
    if (lane >= o) { i1 = fmaxf(i1, u1); i2 = fmaxf(i2, u2); }
  }
  if (lane == 31) { s_w[wid] = i1; s_w[32 + wid] = i2; }
  __syncthreads();
  if (wid == 0) {
    float w1 = s_w[lane], w2 = s_w[32 + lane];
#pragma unroll
    for (int o = 1; o < 32; o <<= 1) {
      float u1 = __shfl_up_sync(0xffffffffu, w1, o);
      float u2 = __shfl_up_sync(0xffffffffu, w2, o);
      if (lane >= o) { w1 = fmaxf(w1, u1); w2 = fmaxf(w2, u2); }
    }
    if (lane == 31) { s_w[64] = w1; s_w[65] = w2; }
    float x1 = __shfl_up_sync(0xffffffffu, w1, 1);
    float x2 = __shfl_up_sync(0xffffffffu, w2, 1);
    if (lane == 0) { x1 = NEG_INF; x2 = NEG_INF; }
    s_w[lane] = x1; s_w[32 + lane] = x2;
  }
  __syncthreads();
  float p1 = __shfl_up_sync(0xffffffffu, i1, 1);
  float p2 = __shfl_up_sync(0xffffffffu, i2, 1);
  if (lane == 0) { p1 = NEG_INF; p2 = NEG_INF; }
  e1 = fmaxf(s_w[wid], p1);
  e2 = fmaxf(s_w[32 + wid], p2);
  tot1 = s_w[64]; tot2 = s_w[65];
}

// fused dual exclusive SUFFIX min scan (min over threads with larger tid) + inclusive totals
__device__ __forceinline__ void bscan2_rev_ex_min(float v1, float v2, float* s_w,
                                                  float& e1, float& e2,
                                                  float& tot1, float& tot2) {
  int lane = threadIdx.x & 31, wid = threadIdx.x >> 5;
  __syncthreads();
  float i1 = v1, i2 = v2;
#pragma unroll
  for (int o = 1; o < 32; o <<= 1) {
    float u1 = __shfl_down_sync(0xffffffffu, i1, o);
    float u2 = __shfl_down_sync(0xffffffffu, i2, o);
    if (lane < 32 - o) { i1 = fminf(i1, u1); i2 = fminf(i2, u2); }
  }
  if (lane == 0) { s_w[wid] = i1; s_w[32 + wid] = i2; }
  __syncthreads();
  if (wid == 0) {
    float w1 = s_w[lane], w2 = s_w[32 + lane];
#pragma unroll
    for (int o = 1; o < 32; o <<= 1) {
      float u1 = __shfl_down_sync(0xffffffffu, w1, o);
      float u2 = __shfl_down_sync(0xffffffffu, w2, o);
      if (lane < 32 - o) { w1 = fminf(w1, u1); w2 = fminf(w2, u2); }
    }
    if (lane == 0) { s_w[64] = w1; s_w[65] = w2; }
    float x1 = __shfl_down_sync(0xffffffffu, w1, 1);
    float x2 = __shfl_down_sync(0xffffffffu, w2, 1);
    if (lane == 31) { x1 = POS_INF; x2 = POS_INF; }
    s_w[lane] = x1; s_w[32 + lane] = x2;
  }
  __syncthreads();
  float p1 = __shfl_down_sync(0xffffffffu, i1, 1);
  float p2 = __shfl_down_sync(0xffffffffu, i2, 1);
  if (lane == 31) { p1 = POS_INF; p2 = POS_INF; }
  e1 = fminf(s_w[wid], p1);
  e2 = fminf(s_w[32 + wid], p2);
  tot1 = s_w[64]; tot2 = s_w[65];
}

__device__ __forceinline__ void bsum2(float v1, float v2, float* s_w,
                                      float& r1, float& r2) {
  int lane = threadIdx.x & 31, wid = threadIdx.x >> 5;
  __syncthreads();
#pragma unroll
  for (int o = 16; o > 0; o >>= 1) {
    v1 += __shfl_down_sync(0xffffffffu, v1, o);
    v2 += __shfl_down_sync(0xffffffffu, v2, o);
  }
  if (lane == 0) { s_w[wid] = v1; s_w[32 + wid] = v2; }
  __syncthreads();
  if (wid == 0) {
    float a = s_w[lane], b = s_w[32 + lane];
#pragma unroll
    for (int o = 16; o > 0; o >>= 1) {
      a += __shfl_down_sync(0xffffffffu, a, o);
      b += __shfl_down_sync(0xffffffffu, b, o);
    }
    if (lane == 0) { s_w[64] = a; s_w[65] = b; }
  }
  __syncthreads();
  r1 = s_w[64]; r2 = s_w[65];
}

// np.interp through peaks, with next-peak value cached per thread
__device__ __forceinline__ float ienv_r(const float* sh, int l, int r, int i,
                                        int& rc, float& vr) {
  if (r != rc) { rc = r; vr = sh[IDX(r >= Ln ? Ln - 1 : r)]; }
  float vl = sh[IDX(l < 0 ? 0 : l)];
  if (r >= Ln) return vl;
  if (l < 0) return vr;
  int den = r - l;
  if (den <= 0) return vl;
  return vl + ((float)(i - l) / (float)den) * (vr - vl);
}

// ---------- main persistent kernel ----------

__global__ void __launch_bounds__(NT, 1)
emd_main(const float* __restrict__ x, float* __restrict__ out) {
  extern __shared__ float dsm[];
  float* P0 = dsm;
  float* P1 = P0 + PADL;       // index buffer / flatness staging
  float* P2 = P1 + PADL;
  __shared__ float s_w[68];
  __shared__ float s_sc;

  const int t = threadIdx.x, row = blockIdx.x;
  const int rb = row * Ln, base = t * CHUNK;
  unsigned nbar = 0;
  int slot = 0;

  for (int i = t; i < Ln; i += NT) g_res[rb + i] = x[rb + i];

  bool done = false;
  for (int k = 0; k < NIMF; k++) {
    float* outk = out + (size_t)k * BATCH * Ln + rb;
    if (done) {
      for (int i = t; i < Ln; i += NT) outk[i] = 0.f;
      continue;
    }
    float* hc = P0;
    float* hn = P2;
    int* ib = (int*)P1;
    for (int i = t; i < Ln; i += NT) hc[IDX(i)] = g_res[rb + i];
    __syncthreads();

    // -------- sifting --------
    for (int it = 0; it < MAXIT; it++) {
      // pass 1: forward walk — running local peak indices + h^2
      float a = (base > 0) ? hc[IDX(base - 1)] : 0.f;
      float b = hc[IDX(base)];
      int lu = -1, ll = -1, fui = Ln, fli = Ln;
      float h2 = 0.f;
#pragma unroll
      for (int j = 0; j < CHUNK; j++) {
        int i = base + j;
        float c = (i + 1 < Ln) ? hc[IDX(i + 1)] : 0.f;
        bool valid = (i > 0) && (i < Ln - 1);
        bool mu = valid && (b > a) && (b > c);
        bool ml = valid && (b < a) && (b < c);
        if (mu) { lu = i; if (fui == Ln) fui = i; }
        if (ml) { ll = i; if (fli == Ln) fli = i; }
        ib[IDX(i)] = (lu + 1) | ((ll + 1) << 16);
        h2 += b * b;
        a = b; b = c;
      }

      float preU, preL, lastU, lastL;
      bscan2_ex_max((float)lu, (float)ll, s_w, preU, preL, lastU, lastL);
      float sufU, sufL, firstU, firstL;
      bscan2_rev_ex_min((float)fui, (float)fli, s_w, sufU, sufL, firstU, firstL);
      int preUi = (int)fmaxf(preU, -1.f), preLi = (int)fmaxf(preL, -1.f);
      int sufUi = (int)fminf(sufU, (float)Ln), sufLi = (int)fminf(sufL, (float)Ln);
      bool manyU = lastU > firstU;   // >=2 upper peaks
      bool manyL = lastL > firstL;   // >=2 lower peaks (block-uniform)

      float m2 = 0.f;
      if (manyU && manyL) {
        // pass 2: backward walk — next-peaks + fused mean + h update
        int i0 = base + CHUNK - 1;
        float b3 = hc[IDX(i0)];
        float c3 = (i0 + 1 < Ln) ? hc[IDX(i0 + 1)] : 0.f;
        int ru = sufUi, rl = sufLi;
        int rcU = -9, rcL = -9; float vrU = 0.f, vrL = 0.f;
#pragma unroll
        for (int j = CHUNK - 1; j >= 0; j--) {
          int i = base + j;
          float a3 = (i > 0) ? hc[IDX(i - 1)] : 0.f;
          bool valid = (i > 0) && (i < Ln - 1);
          if (valid && (b3 > a3) && (b3 > c3)) ru = i;
          if (valid && (b3 < a3) && (b3 < c3)) rl = i;
          unsigned pk = (unsigned)ib[IDX(i)];
          int lui = (pk & 0xffffu) ? (int)(pk & 0xffffu) - 1 : preUi;
          int lli = (pk >> 16) ? (int)(pk >> 16) - 1 : preLi;
          float eu = ienv_r(hc, lui, ru, i, rcU, vrU);
          float el = ienv_r(hc, lli, rl, i, rcL, vrL);
          float m = 0.5f * (eu + el);
          m2 += m * m;
          hn[IDX(i)] = b3 - m;
          c3 = b3; b3 = a3;
        }
      } else {
        // rare paths: env_u -> hn, then combine with env_l
        if (manyU) {
          int i0 = base + CHUNK - 1;
          float b3 = hc[IDX(i0)];
          float c3 = (i0 + 1 < Ln) ? hc[IDX(i0 + 1)] : 0.f;
          int ru = sufUi, rc = -9; float vr = 0.f;
#pragma unroll
          for (int j = CHUNK - 1; j >= 0; j--) {
            int i = base + j;
            float a3 = (i > 0) ? hc[IDX(i - 1)] : 0.f;
            if (i > 0 && i < Ln - 1 && (b3 > a3) && (b3 > c3)) ru = i;
            unsigned pk = (unsigned)ib[IDX(i)];
            int lui = (pk & 0xffffu) ? (int)(pk & 0xffffu) - 1 : preUi;
            hn[IDX(i)] = ienv_r(hc, lui, ru, i, rc, vr);
            c3 = b3; b3 = a3;
          }
        } else {
          float mx = NEG_INF;
#pragma unroll
          for (int j = 0; j < CHUNK; j++) mx = fmaxf(mx, hc[IDX(base + j)]);
          float run = bscan_ex(mx, 1, s_w);
#pragma unroll
          for (int j = 0; j < CHUNK; j++) {
            run = fmaxf(run, hc[IDX(base + j)]);
            hn[IDX(base + j)] = run;
          }
        }
        if (manyL) {
          int i0 = base + CHUNK - 1;
          float b3 = hc[IDX(i0)];
          float c3 = (i0 + 1 < Ln) ? hc[IDX(i0 + 1)] : 0.f;
          int rl = sufLi, rc = -9; float vr = 0.f;
#pragma unroll
          for (int j = CHUNK - 1; j >= 0; j--) {
            int i = base + j;
            float a3 = (i > 0) ? hc[IDX(i - 1)] : 0.f;
            if (i > 0 && i < Ln - 1 && (b3 < a3) && (b3 < c3)) rl = i;
            unsigned pk = (unsigned)ib[IDX(i)];
            int lli = (pk >> 16) ? (int)(pk >> 16) - 1 : preLi;
            float el = ienv_r(hc, lli, rl, i, rc, vr);
            float m = 0.5f * (hn[IDX(i)] + el);
            m2 += m * m;
            hn[IDX(i)] = b3 - m;
            c3 = b3; b3 = a3;
          }
        } else {
          float mn = POS_INF;
#pragma unroll
          for (int j = 0; j < CHUNK; j++) mn = fminf(mn, hc[IDX(base + j)]);
          float run = bscan_ex(mn, 0, s_w);
#pragma unroll
          for (int j = 0; j < CHUNK; j++) {
            int i = base + j;
            float h = hc[IDX(i)];
            run = fminf(run, h);
            float m = 0.5f * (hn[IDX(i)] + run);
            m2 += m * m;
            hn[IDX(i)] = h - m;
          }
        }
      }

      // global sd decision
      float m2T, h2T;
      bsum2(m2, h2, s_w, m2T, h2T);
      nbar++;
      if (t == 0) {
        __stcg(&g_part[slot][0][row], m2T);
        __stcg(&g_part[slot][1][row], h2T);
        __threadfence();
        __stcg(&g_ep[row], nbar);
      }
      if (t < 32) {
        for (;;) {
          unsigned ea = __ldcg(&g_ep[t]);
          unsigned eb = __ldcg(&g_ep[t + 32]);
          if (__all_sync(0xffffffffu, (ea >= nbar) && (eb >= nbar))) break;
          __nanosleep(32);
        }
        __threadfence();
        double A = (double)__ldcg(&g_part[slot][0][t]) + (double)__ldcg(&g_part[slot][0][t + 32]);
        double B = (double)__ldcg(&g_part[slot][1][t]) + (double)__ldcg(&g_part[slot][1][t + 32]);
#pragma unroll
        for (int o = 16; o > 0; o >>= 1) {
          A += __shfl_down_sync(0xffffffffu, A, o);
          B += __shfl_down_sync(0xffffffffu, B, o);
        }
        if (t == 0) s_sc = (A / (B + 1e-8) < TOLF) ? 1.f : 0.f;
      }
      __syncthreads();
      slot ^= 1;
      if (s_sc != 0.f) break;              // keep hc (reference keeps h on conv)
      { float* tmp = hc; hc = hn; hn = tmp; }
    }

    // emit imf = hc, update residual, stage new res into P1 for flatness
    for (int i = t; i < Ln; i += NT) {
      float h = hc[IDX(i)];
      float r = g_res[rb + i] - h;
      outk[i] = h;
      g_res[rb + i] = r;
      P1[IDX(i)] = r;
    }
    __syncthreads();

    float s1 = 0.f, s2 = 0.f, d1 = 0.f, d2 = 0.f;
#pragma unroll
    for (int j = 0; j < CHUNK; j++) {
      int i = base + j;
      float v = P1[IDX(i)];
      s1 += v; s2 += v * v;
      if (i < Ln - 1) { float d = P1[IDX(i + 1)] - v; d1 += d; d2 += d * d; }
    }
    bsum2(s1, s2, s_w, s1, s2);
    bsum2(d1, d2, s_w, d1, d2);
    nbar++;
    if (t == 0) {
      __stcg(&g_part[slot][0][row], s1);
      __stcg(&g_part[slot][1][row], s2);
      __stcg(&g_part[slot][2][row], d1);
      __stcg(&g_part[slot][3][row], d2);
      __threadfence();
      __stcg(&g_ep[row], nbar);
    }
    if (t < 32) {
      for (;;) {
        unsigned ea = __ldcg(&g_ep[t]);
        unsigned eb = __ldcg(&g_ep[t + 32]);
        if (__all_sync(0xffffffffu, (ea >= nbar) && (eb >= nbar))) break;
        __nanosleep(32);
      }
      __threadfence();
      double S1 = (double)__ldcg(&g_part[slot][0][t]) + (double)__ldcg(&g_part[slot][0][t + 32]);
      double S2 = (double)__ldcg(&g_part[slot][1][t]) + (double)__ldcg(&g_part[slot][1][t + 32]);
      double D1 = (double)__ldcg(&g_part[slot][2][t]) + (double)__ldcg(&g_part[slot][2][t + 32]);
      double D2 = (double)__ldcg(&g_part[slot][3][t]) + (double)__ldcg(&g_part[slot][3][t + 32]);
#pragma unroll
      for (int o = 16; o > 0; o >>= 1) {
        S1 += __shfl_down_sync(0xffffffffu, S1, o);
        S2 += __shfl_down_sync(0xffffffffu, S2, o);
        D1 += __shfl_down_sync(0xffffffffu, D1, o);
        D2 += __shfl_down_sync(0xffffffffu, D2, o);
      }
      if (t == 0) {
        double N = (double)BATCH * Ln, Nd = (double)BATCH * (Ln - 1);
        double vr = (S2 - S1 * S1 / N) / (N - 1.0);
        double vd = (D2 - D1 * D1 / Nd) / (Nd - 1.0);
        s_sc = (vd < TOLF * vr) ? 1.f : 0.f;
      }
    }
    __syncthreads();
    slot ^= 1;
    if (s_sc != 0.f) done = true;
  }

  // residual plane
  for (int i = t; i < Ln; i += NT) out[(size_t)NIMF * BATCH * Ln + rb + i] = g_res[rb + i];
}

extern "C" void kernel_launch(void* const* d_in, const int* in_sizes, int n_in,
                              void* d_out, int out_size) {
  const float* x = (const float*)d_in[0];
  float* out = (float*)d_out;
  (void)in_sizes; (void)n_in; (void)out_size;
  cudaFuncSetAttribute(emd_main, cudaFuncAttributeMaxDynamicSharedMemorySize, PADL * 3 * 4);
  emd_init<<<1, BATCH>>>();
  emd_main<<<BATCH, NT, PADL * 3 * 4>>>(x, out);
}

// round 9
// speedup vs baseline: 1.6774x; 1.0656x over previous
#include <cuda_runtime.h>

#define Ln 16384
#define BATCH 64
#define NT 1024
#define CHUNK 16
#define NIMF 6
#define MAXIT 12
#define TOLF 0.05
#define NEG_INF (-3.402823466e38f)
#define POS_INF (3.402823466e38f)
#define IDX(i) ((i)+((i)>>4))
#define PADL (Ln+(Ln>>4))

__device__ unsigned g_ep[BATCH];
__device__ float g_part[2][4][BATCH];
__device__ float g_res[BATCH*Ln];

__global__ void emd_init() { if (threadIdx.x < BATCH) g_ep[threadIdx.x] = 0u; }

// ---------- block primitives ----------

// single-value exclusive prefix scan (rare fallback paths only)
__device__ __forceinline__ float bscan_ex(float v, int ismax, float* s_w) {
  const float ident = ismax ? NEG_INF : POS_INF;
  int lane = threadIdx.x & 31, wid = threadIdx.x >> 5;
  __syncthreads();
  float incl = v;
#pragma unroll
  for (int o = 1; o < 32; o <<= 1) {
    float u = __shfl_up_sync(0xffffffffu, incl, o);
    if (lane >= o) incl = ismax ? fmaxf(incl, u) : fminf(incl, u);
  }
  if (lane == 31) s_w[wid] = incl;
  __syncthreads();
  if (wid == 0) {
    float wi = s_w[lane];
#pragma unroll
    for (int o = 1; o < 32; o <<= 1) {
      float u = __shfl_up_sync(0xffffffffu, wi, o);
      if (lane >= o) wi = ismax ? fmaxf(wi, u) : fminf(wi, u);
    }
    float we = __shfl_up_sync(0xffffffffu, wi, 1);
    if (lane == 0) we = ident;
    s_w[lane] = we;
  }
  __syncthreads();
  float e = __shfl_up_sync(0xffffffffu, incl, 1);
  if (lane == 0) e = ident;
  float wp = s_w[wid];
  return ismax ? fmaxf(wp, e) : fminf(wp, e);
}

// fused quad scan: exclusive prefix-MAX on (v1,v2), exclusive suffix-MIN on (v3,v4),
// plus block-wide inclusive totals of each. 2 internal syncs.
// Caller guarantees s_w[0..131] is free at entry (protected by surrounding barriers).
__device__ __forceinline__ void bscan4(float v1, float v2, float v3, float v4, float* s_w,
                                       float& e1, float& e2, float& e3, float& e4,
                                       float& tot1, float& tot2, float& tot3, float& tot4) {
  int lane = threadIdx.x & 31, wid = threadIdx.x >> 5;
  float a1 = v1, a2 = v2, b1 = v3, b2 = v4;
#pragma unroll
  for (int o = 1; o < 32; o <<= 1) {
    float u1 = __shfl_up_sync(0xffffffffu, a1, o);
    float u2 = __shfl_up_sync(0xffffffffu, a2, o);
    float d1 = __shfl_down_sync(0xffffffffu, b1, o);
    float d2 = __shfl_down_sync(0xffffffffu, b2, o);
    if (lane >= o) { a1 = fmaxf(a1, u1); a2 = fmaxf(a2, u2); }
    if (lane < 32 - o) { b1 = fminf(b1, d1); b2 = fminf(b2, d2); }
  }
  if (lane == 31) { s_w[wid] = a1; s_w[32 + wid] = a2; }
  if (lane == 0)  { s_w[64 + wid] = b1; s_w[96 + wid] = b2; }
  __syncthreads();
  if (wid == 0) {
    float w1 = s_w[lane], w2 = s_w[32 + lane], w3 = s_w[64 + lane], w4 = s_w[96 + lane];
#pragma unroll
    for (int o = 1; o < 32; o <<= 1) {
      float u1 = __shfl_up_sync(0xffffffffu, w1, o);
      float u2 = __shfl_up_sync(0xffffffffu, w2, o);
      float d3 = __shfl_down_sync(0xffffffffu, w3, o);
      float d4 = __shfl_down_sync(0xffffffffu, w4, o);
      if (lane >= o) { w1 = fmaxf(w1, u1); w2 = fmaxf(w2, u2); }
      if (lane < 32 - o) { w3 = fminf(w3, d3); w4 = fminf(w4, d4); }
    }
    if (lane == 31) { s_w[128] = w1; s_w[129] = w2; }
    if (lane == 0)  { s_w[130] = w3; s_w[131] = w4; }
    float x1 = __shfl_up_sync(0xffffffffu, w1, 1);
    float x2 = __shfl_up_sync(0xffffffffu, w2, 1);
    float x3 = __shfl_down_sync(0xffffffffu, w3, 1);
    float x4 = __shfl_down_sync(0xffffffffu, w4, 1);
    if (lane == 0)  { x1 = NEG_INF; x2 = NEG_INF; }
    if (lane == 31) { x3 = POS_INF; x4 = POS_INF; }
    s_w[lane] = x1; s_w[32 + lane] = x2; s_w[64 + lane] = x3; s_w[96 + lane] = x4;
  }
  __syncthreads();
  float p1 = __shfl_up_sync(0xffffffffu, a1, 1);
  float p2 = __shfl_up_sync(0xffffffffu, a2, 1);
  float q1 = __shfl_down_sync(0xffffffffu, b1, 1);
  float q2 = __shfl_down_sync(0xffffffffu, b2, 1);
  if (lane == 0)  { p1 = NEG_INF; p2 = NEG_INF; }
  if (lane == 31) { q1 = POS_INF; q2 = POS_INF; }
  e1 = fmaxf(s_w[wid], p1);
  e2 = fmaxf(s_w[32 + wid], p2);
  e3 = fminf(s_w[64 + wid], q1);
  e4 = fminf(s_w[96 + wid], q2);
  tot1 = s_w[128]; tot2 = s_w[129]; tot3 = s_w[130]; tot4 = s_w[131];
}

__device__ __forceinline__ void bsum2(float v1, float v2, float* s_w,
                                      float& r1, float& r2) {
  int lane = threadIdx.x & 31, wid = threadIdx.x >> 5;
  __syncthreads();
#pragma unroll
  for (int o = 16; o > 0; o >>= 1) {
    v1 += __shfl_down_sync(0xffffffffu, v1, o);
    v2 += __shfl_down_sync(0xffffffffu, v2, o);
  }
  if (lane == 0) { s_w[wid] = v1; s_w[32 + wid] = v2; }
  __syncthreads();
  if (wid == 0) {
    float a = s_w[lane], b = s_w[32 + lane];
#pragma unroll
    for (int o = 16; o > 0; o >>= 1) {
      a += __shfl_down_sync(0xffffffffu, a, o);
      b += __shfl_down_sync(0xffffffffu, b, o);
    }
    if (lane == 0) { s_w[64] = a; s_w[65] = b; }
  }
  __syncthreads();
  r1 = s_w[64]; r2 = s_w[65];
}

// np.interp through peaks; vl/vr reloaded only when l/r change. Arithmetic
// expression identical to the previously-verified version (bitwise-safe).
__device__ __forceinline__ float seg_env(const float* h, int l, int r, int i,
                                         int& cl, int& cr, float& vl, float& vr) {
  if (r != cr) { cr = r; vr = h[IDX(r >= Ln ? Ln - 1 : r)]; }
  if (l != cl) { cl = l; vl = h[IDX(l < 0 ? 0 : l)]; }
  if (r >= Ln) return vl;
  if (l < 0) return vr;
  int den = r - l;
  if (den <= 0) return vl;
  return vl + ((float)(i - l) / (float)den) * (vr - vl);
}

// ---------- main persistent kernel ----------

__global__ void __launch_bounds__(NT, 1)
emd_main(const float* __restrict__ x, float* __restrict__ out) {
  extern __shared__ float dsm[];
  float* P0 = dsm;
  float* P1 = P0 + PADL;           // ib (peak-index buffer)
  float* P2 = P1 + PADL;
  __shared__ float s_w[132];
  __shared__ float s_sc;

  const int t = threadIdx.x, row = blockIdx.x;
  const int rb = row * Ln, base = t * CHUNK;
  const int lane = t & 31;
  unsigned nbar = 0;

  float* hc = P0;
  float* hn = P2;
  int* ib = (int*)P1;

  for (int i = t; i < Ln; i += NT) {
    float v = x[rb + i];
    g_res[rb + i] = v;
    hc[IDX(i)] = v;
  }

  // pass-1 state (fed into scans): per-thread running peak info + sum(h^2)
  float lu, ll, fu, fl, h2;
  auto pass1 = [&](const float* h) {
    float a = (base > 0) ? h[IDX(base - 1)] : 0.f;
    float b = h[IDX(base)];
    int lui = -1, lli = -1, fui = Ln, fli = Ln;
    float s = 0.f;
#pragma unroll
    for (int j = 0; j < CHUNK; j++) {
      int i = base + j;
      float c = (i + 1 < Ln) ? h[IDX(i + 1)] : 0.f;
      bool valid = (i > 0) && (i < Ln - 1);
      bool mu = valid && (b > a) && (b > c);
      bool ml = valid && (b < a) && (b < c);
      if (mu) { lui = i; if (fui == Ln) fui = i; }
      if (ml) { lli = i; if (fli == Ln) fli = i; }
      ib[IDX(i)] = (lui + 1) | ((lli + 1) << 16);
      s += b * b;
      a = b; b = c;
    }
    lu = (float)lui; ll = (float)lli; fu = (float)fui; fl = (float)fli; h2 = s;
  };

  bool done = false;
  for (int k = 0; k < NIMF; k++) {
    float* outk = out + (size_t)k * BATCH * Ln + rb;
    if (done) {
      for (int i = t; i < Ln; i += NT) outk[i] = 0.f;
      continue;
    }
    __syncthreads();          // hc fully written (init or previous emit)
    pass1(hc);

    // -------- sifting --------
    for (int it = 0; it < MAXIT; it++) {
      float preU, preL, sufU, sufL, lastU, lastL, firstU, firstL;
      bscan4(lu, ll, fu, fl, s_w, preU, preL, sufU, sufL, lastU, lastL, firstU, firstL);
      int preUi = (int)fmaxf(preU, -1.f), preLi = (int)fmaxf(preL, -1.f);
      int sufUi = (int)fminf(sufU, (float)Ln), sufLi = (int)fminf(sufL, (float)Ln);
      bool manyU = lastU > firstU;    // >=2 upper peaks (block-uniform)
      bool manyL = lastL > firstL;

      float m2 = 0.f;
      if (manyU && manyL) {
        // pass 2: backward walk — next-peaks + fused mean + h update into hn
        int i0 = base + CHUNK - 1;
        float b3 = hc[IDX(i0)];
        float c3 = (i0 + 1 < Ln) ? hc[IDX(i0 + 1)] : 0.f;
        int ru = sufUi, rl = sufLi;
        int clU = -9, crU = -9, clL = -9, crL = -9;
        float vlU = 0.f, vrU = 0.f, vlL = 0.f, vrL = 0.f;
#pragma unroll
        for (int j = CHUNK - 1; j >= 0; j--) {
          int i = base + j;
          float a3 = (i > 0) ? hc[IDX(i - 1)] : 0.f;
          bool valid = (i > 0) && (i < Ln - 1);
          if (valid && (b3 > a3) && (b3 > c3)) ru = i;
          if (valid && (b3 < a3) && (b3 < c3)) rl = i;
          unsigned pk = (unsigned)ib[IDX(i)];
          int lui = (pk & 0xffffu) ? (int)(pk & 0xffffu) - 1 : preUi;
          int lli = (pk >> 16) ? (int)(pk >> 16) - 1 : preLi;
          float eu = seg_env(hc, lui, ru, i, clU, crU, vlU, vrU);
          float el = seg_env(hc, lli, rl, i, clL, crL, vlL, vrL);
          float m = 0.5f * (eu + el);
          m2 += m * m;
          hn[IDX(i)] = b3 - m;
          c3 = b3; b3 = a3;
        }
      } else {
        // rare paths: env_u -> hn, then combine with env_l
        if (manyU) {
          int i0 = base + CHUNK - 1;
          float b3 = hc[IDX(i0)];
          float c3 = (i0 + 1 < Ln) ? hc[IDX(i0 + 1)] : 0.f;
          int ru = sufUi, cl = -9, cr = -9;
          float vl = 0.f, vr = 0.f;
#pragma unroll
          for (int j = CHUNK - 1; j >= 0; j--) {
            int i = base + j;
            float a3 = (i > 0) ? hc[IDX(i - 1)] : 0.f;
            if (i > 0 && i < Ln - 1 && (b3 > a3) && (b3 > c3)) ru = i;
            unsigned pk = (unsigned)ib[IDX(i)];
            int lui = (pk & 0xffffu) ? (int)(pk & 0xffffu) - 1 : preUi;
            hn[IDX(i)] = seg_env(hc, lui, ru, i, cl, cr, vl, vr);
            c3 = b3; b3 = a3;
          }
        } else {
          float mx = NEG_INF;
#pragma unroll
          for (int j = 0; j < CHUNK; j++) mx = fmaxf(mx, hc[IDX(base + j)]);
          float run = bscan_ex(mx, 1, s_w);
#pragma unroll
          for (int j = 0; j < CHUNK; j++) {
            run = fmaxf(run, hc[IDX(base + j)]);
            hn[IDX(base + j)] = run;
          }
        }
        if (manyL) {
          int i0 = base + CHUNK - 1;
          float b3 = hc[IDX(i0)];
          float c3 = (i0 + 1 < Ln) ? hc[IDX(i0 + 1)] : 0.f;
          int rl = sufLi, cl = -9, cr = -9;
          float vl = 0.f, vr = 0.f;
#pragma unroll
          for (int j = CHUNK - 1; j >= 0; j--) {
            int i = base + j;
            float a3 = (i > 0) ? hc[IDX(i - 1)] : 0.f;
            if (i > 0 && i < Ln - 1 && (b3 < a3) && (b3 < c3)) rl = i;
            unsigned pk = (unsigned)ib[IDX(i)];
            int lli = (pk >> 16) ? (int)(pk >> 16) - 1 : preLi;
            float el = seg_env(hc, lli, rl, i, cl, cr, vl, vr);
            float m = 0.5f * (hn[IDX(i)] + el);
            m2 += m * m;
            hn[IDX(i)] = b3 - m;
            c3 = b3; b3 = a3;
          }
        } else {
          float mn = POS_INF;
#pragma unroll
          for (int j = 0; j < CHUNK; j++) mn = fminf(mn, hc[IDX(base + j)]);
          float run = bscan_ex(mn, 0, s_w);
#pragma unroll
          for (int j = 0; j < CHUNK; j++) {
            int i = base + j;
            float h = hc[IDX(i)];
            run = fminf(run, h);
            float m = 0.5f * (hn[IDX(i)] + run);
            m2 += m * m;
            hn[IDX(i)] = h - m;
          }
        }
      }

      // warp-level partials of (m2, h2) -> s_w[0..63]
      {
        float w1 = m2, w2 = h2;
#pragma unroll
        for (int o = 16; o > 0; o >>= 1) {
          w1 += __shfl_down_sync(0xffffffffu, w1, o);
          w2 += __shfl_down_sync(0xffffffffu, w2, o);
        }
        if (lane == 0) { s_w[t >> 5] = w1; s_w[32 + (t >> 5)] = w2; }
      }
      __syncthreads();                    // hn + partials visible
      nbar++;
      int slot = (int)(nbar & 1u);
      if (t < 32) {
        // finalize block sums, post, poll, decide — overlapped with others' pass1
        float a = s_w[t], b = s_w[32 + t];
#pragma unroll
        for (int o = 16; o > 0; o >>= 1) {
          a += __shfl_down_sync(0xffffffffu, a, o);
          b += __shfl_down_sync(0xffffffffu, b, o);
        }
        if (t == 0) {
          __stcg(&g_part[slot][0][row], a);
          __stcg(&g_part[slot][1][row], b);
          __threadfence();
          __stcg(&g_ep[row], nbar);
        }
        for (;;) {
          unsigned ea = __ldcg(&g_ep[t]);
          unsigned eb = __ldcg(&g_ep[t + 32]);
          if (__all_sync(0xffffffffu, (ea >= nbar) && (eb >= nbar))) break;
          __nanosleep(32);
        }
        __threadfence();
        double A = (double)__ldcg(&g_part[slot][0][t]) + (double)__ldcg(&g_part[slot][0][t + 32]);
        double B = (double)__ldcg(&g_part[slot][1][t]) + (double)__ldcg(&g_part[slot][1][t + 32]);
#pragma unroll
        for (int o = 16; o > 0; o >>= 1) {
          A += __shfl_down_sync(0xffffffffu, A, o);
          B += __shfl_down_sync(0xffffffffu, B, o);
        }
        if (t == 0) s_sc = (A / (B + 1e-8) < TOLF) ? 1.f : 0.f;
      }
      // speculative pass 1 on hn (overlaps the poll above); discarded on conv
      pass1(hn);
      __syncthreads();
      if (s_sc != 0.f) break;             // converged: keep hc
      { float* tmp = hc; hc = hn; hn = tmp; }  // h2/lu/ll/fu/fl now describe new hc
    }

    // emit imf = hc, update residual, stage r into hn (becomes next IMF's h)
    for (int i = t; i < Ln; i += NT) {
      float h = hc[IDX(i)];
      float r = g_res[rb + i] - h;
      outk[i] = h;
      g_res[rb + i] = r;
      hn[IDX(i)] = r;
    }
    __syncthreads();

    // flatness: var(diff(res), ddof=1) < TOL * var(res, ddof=1), global
    float s1 = 0.f, s2 = 0.f, d1 = 0.f, d2 = 0.f;
#pragma unroll
    for (int j = 0; j < CHUNK; j++) {
      int i = base + j;
      float v = hn[IDX(i)];
      s1 += v; s2 += v * v;
      if (i < Ln - 1) { float d = hn[IDX(i + 1)] - v; d1 += d; d2 += d * d; }
    }
    bsum2(s1, s2, s_w, s1, s2);
    bsum2(d1, d2, s_w, d1, d2);
    nbar++;
    int slot = (int)(nbar & 1u);
    if (t == 0) {
      __stcg(&g_part[slot][0][row], s1);
      __stcg(&g_part[slot][1][row], s2);
      __stcg(&g_part[slot][2][row], d1);
      __stcg(&g_part[slot][3][row], d2);
      __threadfence();
      __stcg(&g_ep[row], nbar);
    }
    if (t < 32) {
      for (;;) {
        unsigned ea = __ldcg(&g_ep[t]);
        unsigned eb = __ldcg(&g_ep[t + 32]);
        if (__all_sync(0xffffffffu, (ea >= nbar) && (eb >= nbar))) break;
        __nanosleep(32);
      }
      __threadfence();
      double S1 = (double)__ldcg(&g_part[slot][0][t]) + (double)__ldcg(&g_part[slot][0][t + 32]);
      double S2 = (double)__ldcg(&g_part[slot][1][t]) + (double)__ldcg(&g_part[slot][1][t + 32]);
      double D1 = (double)__ldcg(&g_part[slot][2][t]) + (double)__ldcg(&g_part[slot][2][t + 32]);
      double D2 = (double)__ldcg(&g_part[slot][3][t]) + (double)__ldcg(&g_part[slot][3][t + 32]);
#pragma unroll
      for (int o = 16; o > 0; o >>= 1) {
        S1 += __shfl_down_sync(0xffffffffu, S1, o);
        S2 += __shfl_down_sync(0xffffffffu, S2, o);
        D1 += __shfl_down_sync(0xffffffffu, D1, o);
        D2 += __shfl_down_sync(0xffffffffu, D2, o);
      }
      if (t == 0) {
        double N = (double)BATCH * Ln, Nd = (double)BATCH * (Ln - 1);
        double vr = (S2 - S1 * S1 / N) / (N - 1.0);
        double vd = (D2 - D1 * D1 / Nd) / (Nd - 1.0);
        s_sc = (vd < TOLF * vr) ? 1.f : 0.f;
      }
    }
    __syncthreads();
    if (s_sc != 0.f) done = true;
    { float* tmp = hc; hc = hn; hn = tmp; }   // hc := residual (next IMF's h)
  }

  // residual plane
  for (int i = t; i < Ln; i += NT) out[(size_t)NIMF * BATCH * Ln + rb + i] = g_res[rb + i];
}

extern "C" void kernel_launch(void* const* d_in, const int* in_sizes, int n_in,
                              void* d_out, int out_size) {
  const float* x = (const float*)d_in[0];
  float* out = (float*)d_out;
  (void)in_sizes; (void)n_in; (void)out_size;
  cudaFuncSetAttribute(emd_main, cudaFuncAttributeMaxDynamicSharedMemorySize, PADL * 3 * 4);
  emd_init<<<1, BATCH>>>();
  emd_main<<<BATCH, NT, PADL * 3 * 4>>>(x, out);
}